// round 14
// baseline (speedup 1.0000x reference)
#include <cuda_runtime.h>
#include <cuda_bf16.h>
#include <cstdint>

#define NPTS 8192
#define D 200
#define ROW_BYTES 512              // bf16 rows zero-padded to 256 k in global
#define TM 128
#define NT (NPTS / TM)             // 64
#define NTRI (NT * (NT + 1) / 2)   // 2080
#define TPB 256
#define SROW 144                   // 128B chunk row + 16 pad -> conflict-free
#define ACH (TM * SROW)            // 18432
#define STAGE (2 * ACH)            // A + B per stage = 36864
#define SMEM_DYN (2 * STAGE)       // double buffer = 73728

// ---------------- device scratch (no allocations allowed) ----------------
__device__ __align__(16) unsigned char g_xb[(size_t)NPTS * ROW_BYTES]; // 4 MB bf16
__device__ float g_sq[NPTS];
__device__ float g_part[NTRI];
__device__ int   g_is64;
__device__ unsigned int g_cnt;

#define CP16(d, s) \
    asm volatile("cp.async.cg.shared.global [%0], [%1], 16;" :: "r"(d), "l"(s) : "memory")
#define CPC()  asm volatile("cp.async.commit_group;" ::: "memory")
#define CPW1() asm volatile("cp.async.wait_group 1;" ::: "memory")
#define CPW0() asm volatile("cp.async.wait_group 0;" ::: "memory")

// ---------------------------------------------------------------------------
// Kernel 1: x -> bf16 (zero-padded), sq from the SAME bf16 values.
// Block 0 additionally: label-dtype detection + counter reset.
// ---------------------------------------------------------------------------
__global__ void prep_kernel(const float* __restrict__ x,
                            const int* __restrict__ lab32) {
    int row  = blockIdx.x * (TPB / 32) + (threadIdx.x >> 5);
    int lane = threadIdx.x & 31;
    int k0   = lane * 8;
    const float* xr = x + (size_t)row * D;
    float s = 0.f;
    uint32_t w[4];
#pragma unroll
    for (int p = 0; p < 4; p++) {
        int ka = k0 + 2 * p, kb = ka + 1;
        float f0 = (ka < D) ? xr[ka] : 0.f;
        float f1 = (kb < D) ? xr[kb] : 0.f;
        __nv_bfloat16 b0 = __float2bfloat16(f0);
        __nv_bfloat16 b1 = __float2bfloat16(f1);
        float g0 = __bfloat162float(b0), g1 = __bfloat162float(b1);
        s = fmaf(g0, g0, s);
        s = fmaf(g1, g1, s);
        w[p] = (uint32_t)__bfloat16_as_ushort(b0) |
               ((uint32_t)__bfloat16_as_ushort(b1) << 16);
    }
    *(uint4*)(g_xb + (size_t)row * ROW_BYTES + k0 * 2) = make_uint4(w[0], w[1], w[2], w[3]);
#pragma unroll
    for (int o = 16; o; o >>= 1) s += __shfl_xor_sync(0xffffffffu, s, o);
    if (lane == 0) g_sq[row] = s;

    if (blockIdx.x == 0) {  // label dtype detection + counter reset
        __shared__ int any;
        if (threadIdx.x == 0) { any = 0; g_cnt = 0; }
        __syncthreads();
        int a = 0;
        for (int i = 2 * threadIdx.x + 1; i < NPTS; i += 2 * TPB) a |= lab32[i];
        if (a) atomicOr(&any, 1);
        __syncthreads();
        if (threadIdx.x == 0) g_is64 = (any == 0) ? 1 : 0;
    }
}

// ---------------------------------------------------------------------------
// Chunk prefetch: thread t -> operand (t>>7), row (t&127), 8 x 16B.
// ---------------------------------------------------------------------------
__device__ __forceinline__ void prefetch(uint32_t dynA, int buf,
                                         const unsigned char* gA,
                                         const unsigned char* gB, int ch, int t) {
    int row = t & 127, op = t >> 7;
    const unsigned char* src = (op ? gB : gA) + (size_t)row * ROW_BYTES + (size_t)ch * 128;
    uint32_t dst = dynA + (buf ? (uint32_t)STAGE : 0u) + (op ? (uint32_t)ACH : 0u)
                 + row * SROW;
#pragma unroll
    for (int c = 0; c < 8; c++)
        CP16(dst + c * 16, src + c * 16);
    CPC();
}

// ---------------------------------------------------------------------------
// Kernel 2: triangular grid of 128x128 Gram tiles, mma.sync bf16 m16n8k16.
// cp.async double buffer; B-fragment ring (lookahead 2), A one kstep ahead.
// Off-diagonal tiles get a predicate-free lean epilogue.
// ---------------------------------------------------------------------------
__global__ void __launch_bounds__(TPB, 2)
pair_kernel(const int* __restrict__ lab32, float* __restrict__ out) {
    extern __shared__ __align__(128) unsigned char dyn[];
    __shared__ float sqA[TM], sqB[TM];
    __shared__ int   lA[TM], lB[TM];
    __shared__ float red[TPB / 32];
    __shared__ int    s_last;
    __shared__ double dred[TPB];

    const int t    = threadIdx.x;
    const int wid  = t >> 5;
    const int lane = t & 31;

    // linearized upper-triangle map: blockIdx.x -> (ti, tj), ti <= tj
    int bl = blockIdx.x, ti = 0;
    while (bl >= NT - ti) { bl -= NT - ti; ti++; }
    const int tj = ti + bl;

    const uint32_t dynA = (uint32_t)__cvta_generic_to_shared(dyn);
    const unsigned char* gA = g_xb + (size_t)(ti * TM) * ROW_BYTES;
    const unsigned char* gB = g_xb + (size_t)(tj * TM) * ROW_BYTES;

    prefetch(dynA, 0, gA, gB, 0, t);
    prefetch(dynA, 1, gA, gB, 1, t);

    {
        int is64 = g_is64;
        if (t < TM) {
            int g = ti * TM + t;
            sqA[t] = g_sq[g];
            lA[t]  = is64 ? lab32[2 * g] : lab32[g];
        } else {
            int u = t - TM, g = tj * TM + u;
            sqB[u] = g_sq[g];
            lB[u]  = is64 ? lab32[2 * g] : lab32[g];
        }
    }

    const int warp_m = wid >> 1;   // 0..3 -> 32 rows
    const int warp_n = wid & 1;    // 0..1 -> 64 cols

    uint32_t abase[2];
#pragma unroll
    for (int f = 0; f < 2; f++)
        abase[f] = dynA + (warp_m * 32 + f * 16 + (lane & 15)) * SROW
                 + ((lane >> 4) << 4);
    uint32_t bbase[4];
#pragma unroll
    for (int h = 0; h < 4; h++)
        bbase[h] = dynA + ACH
                 + (warp_n * 64 + h * 16 + (lane & 7) + ((lane >> 4) << 3)) * SROW
                 + (((lane >> 3) & 1) << 4);

    float acc[2][8][4];
#pragma unroll
    for (int f = 0; f < 2; f++)
#pragma unroll
        for (int j = 0; j < 8; j++)
#pragma unroll
            for (int e = 0; e < 4; e++) acc[f][j][e] = 0.f;

    uint32_t aF[2][2][4];   // [kstep parity][f][frag]
    uint32_t bF[3][4];      // ring of 3 stages

#define LDA_M(buf, kk)                                                            \
    { _Pragma("unroll")                                                           \
      for (int f = 0; f < 2; f++)                                                 \
          asm volatile("ldmatrix.sync.aligned.m8n8.x4.shared.b16 {%0,%1,%2,%3}, [%4];" \
              : "=r"(aF[buf][f][0]), "=r"(aF[buf][f][1]),                         \
                "=r"(aF[buf][f][2]), "=r"(aF[buf][f][3])                          \
              : "r"(ab[f] + (kk) * 32)); }

#define LDB_M(slot, kk, hh)                                                       \
    asm volatile("ldmatrix.sync.aligned.m8n8.x4.shared.b16 {%0,%1,%2,%3}, [%4];"  \
        : "=r"(bF[slot][0]), "=r"(bF[slot][1]), "=r"(bF[slot][2]), "=r"(bF[slot][3]) \
        : "r"(bb[hh] + (kk) * 32))

#define MMA4_M(abuf, slot, hh)                                                    \
    { _Pragma("unroll")                                                           \
      for (int f = 0; f < 2; f++) {                                               \
          asm volatile(                                                           \
              "mma.sync.aligned.m16n8k16.row.col.f32.bf16.bf16.f32 "              \
              "{%0,%1,%2,%3}, {%4,%5,%6,%7}, {%8,%9}, {%0,%1,%2,%3};"             \
              : "+f"(acc[f][2 * (hh)][0]), "+f"(acc[f][2 * (hh)][1]),             \
                "+f"(acc[f][2 * (hh)][2]), "+f"(acc[f][2 * (hh)][3])              \
              : "r"(aF[abuf][f][0]), "r"(aF[abuf][f][1]),                         \
                "r"(aF[abuf][f][2]), "r"(aF[abuf][f][3]),                         \
                "r"(bF[slot][0]), "r"(bF[slot][1]));                              \
          asm volatile(                                                           \
              "mma.sync.aligned.m16n8k16.row.col.f32.bf16.bf16.f32 "              \
              "{%0,%1,%2,%3}, {%4,%5,%6,%7}, {%8,%9}, {%0,%1,%2,%3};"             \
              : "+f"(acc[f][2 * (hh) + 1][0]), "+f"(acc[f][2 * (hh) + 1][1]),     \
                "+f"(acc[f][2 * (hh) + 1][2]), "+f"(acc[f][2 * (hh) + 1][3])      \
              : "r"(aF[abuf][f][0]), "r"(aF[abuf][f][1]),                         \
                "r"(aF[abuf][f][2]), "r"(aF[abuf][f][3]),                         \
                "r"(bF[slot][2]), "r"(bF[slot][3]));                              \
      } }

// Pipelined chunk: lookahead-2 B ring, A loaded one kstep early.
#define CHUNK_M(NS)                                                               \
    do {                                                                          \
        LDA_M(0, 0);                                                              \
        LDB_M(0, 0, 0);                                                           \
        LDB_M(1, 0, 1);                                                           \
        _Pragma("unroll")                                                         \
        for (int s = 0; s < 4 * (NS); s++) {                                      \
            int ks = s >> 2, h = s & 3;                                           \
            if (h == 0 && ks + 1 < (NS)) LDA_M((ks + 1) & 1, ks + 1);             \
            int sn = s + 2;                                                       \
            if (sn < 4 * (NS)) LDB_M(sn % 3, sn >> 2, sn & 3);                    \
            MMA4_M(ks & 1, s % 3, h);                                             \
        }                                                                         \
    } while (0)

#pragma unroll
    for (int ch = 0; ch < 4; ch++) {
        if (ch < 3) CPW1(); else CPW0();
        __syncthreads();
        const uint32_t bofs = (ch & 1) ? (uint32_t)STAGE : 0u;
        uint32_t ab[2] = {abase[0] + bofs, abase[1] + bofs};
        uint32_t bb[4] = {bbase[0] + bofs, bbase[1] + bofs,
                          bbase[2] + bofs, bbase[3] + bofs};
        if (ch < 3) CHUNK_M(4); else CHUNK_M(1);   // 13 k-steps total
        __syncthreads();
        if (ch < 2) prefetch(dynA, ch & 1, gA, gB, ch + 2, t);
    }
#undef CHUNK_M
#undef MMA4_M
#undef LDB_M
#undef LDA_M

    // ---- Lean epilogue: hoist stats into regs, 4 partial sums ----
    const int qrow = lane >> 2;
    const int qcol = (lane & 3) * 2;
    float sA4[4]; int lA4[4];
#pragma unroll
    for (int r = 0; r < 4; r++) {
        int m = warp_m * 32 + (r >> 1) * 16 + (r & 1) * 8 + qrow;
        sA4[r] = sqA[m];
        lA4[r] = lA[m];
    }
    float sB16[16]; int lB16[16];
#pragma unroll
    for (int c = 0; c < 16; c++) {
        int n = warp_n * 64 + (c >> 1) * 8 + (c & 1) + qcol;
        sB16[c] = sqB[n];
        lB16[c] = lB[n];
    }
    float ps[4] = {0.f, 0.f, 0.f, 0.f};
    if (ti != tj) {  // hot path: every element counts, no index math
#pragma unroll
        for (int f = 0; f < 2; f++)
#pragma unroll
            for (int j = 0; j < 8; j++)
#pragma unroll
                for (int e = 0; e < 4; e++) {
                    int r = f * 2 + (e >> 1);
                    int c = j * 2 + (e & 1);
                    float d2 = fmaf(-2.f, acc[f][j][e], sA4[r] + sB16[c]);
                    float dist;
                    asm("sqrt.approx.f32 %0, %1;" : "=f"(dist) : "f"(d2));
                    ps[e] += (lA4[r] == lB16[c]) ? dist : -dist;
                }
    } else {         // 64 diagonal tiles: strict upper predicate
#pragma unroll
        for (int f = 0; f < 2; f++)
#pragma unroll
            for (int j = 0; j < 8; j++)
#pragma unroll
                for (int e = 0; e < 4; e++) {
                    int r = f * 2 + (e >> 1);
                    int c = j * 2 + (e & 1);
                    int m_loc = warp_m * 32 + (r >> 1) * 16 + (r & 1) * 8 + qrow;
                    int n_loc = warp_n * 64 + (c >> 1) * 8 + (c & 1) + qcol;
                    float d2 = fmaxf(fmaf(-2.f, acc[f][j][e], sA4[r] + sB16[c]), 0.f);
                    float dist;
                    asm("sqrt.approx.f32 %0, %1;" : "=f"(dist) : "f"(d2));
                    float sgn = (lA4[r] == lB16[c]) ? dist : -dist;
                    if (n_loc > m_loc) ps[e] += sgn;
                }
    }
    float lsum = (ps[0] + ps[1]) + (ps[2] + ps[3]);
#pragma unroll
    for (int o = 16; o; o >>= 1) lsum += __shfl_xor_sync(0xffffffffu, lsum, o);
    if (lane == 0) red[wid] = lsum;
    __syncthreads();
    if (t == 0) {
        float s = 0.f;
#pragma unroll
        for (int w = 0; w < TPB / 32; w++) s += red[w];
        g_part[blockIdx.x] = s;
    }

    // ---- last-CTA-done fused final reduction (deterministic order) ----
    __threadfence();
    if (t == 0) {
        unsigned old = atomicAdd(&g_cnt, 1u);
        s_last = (old == NTRI - 1) ? 1 : 0;
    }
    __syncthreads();
    if (s_last) {
        __threadfence();
        double a = 0.0;
        for (int i = t; i < NTRI; i += TPB) a += (double)g_part[i];
        dred[t] = a;
        __syncthreads();
        for (int o = TPB / 2; o; o >>= 1) {
            if (t < o) dred[t] += dred[t + o];
            __syncthreads();
        }
        if (t == 0) out[0] = (float)(2.0 * dred[0] / (double)NPTS);
    }
}

// ---------------------------------------------------------------------------
extern "C" void kernel_launch(void* const* d_in, const int* in_sizes, int n_in,
                              void* d_out, int out_size) {
    const float* x     = (const float*)d_in[0];
    const int*   lab32 = (const int*)d_in[1];
    float*       outp  = (float*)d_out;

    cudaFuncSetAttribute(pair_kernel, cudaFuncAttributeMaxDynamicSharedMemorySize,
                         SMEM_DYN);

    prep_kernel<<<NPTS / (TPB / 32), TPB>>>(x, lab32);
    pair_kernel<<<NTRI, TPB, SMEM_DYN>>>(lab32, outp);
}

// round 15
// speedup vs baseline: 1.4291x; 1.4291x over previous
#include <cuda_runtime.h>
#include <cuda_bf16.h>
#include <cstdint>

#define NPTS 8192
#define D 200
#define ROW_BYTES 512              // bf16 rows zero-padded to 256 k in global
#define TM 128
#define NT (NPTS / TM)             // 64
#define NTRI (NT * (NT + 1) / 2)   // 2080
#define TPB 256
#define SROW 144                   // 128B chunk row + 16 pad -> conflict-free
#define ACH (TM * SROW)            // 18432
#define STAGE (2 * ACH)            // A + B per stage = 36864
#define SMEM_DYN (2 * STAGE)       // double buffer = 73728

// ---------------- device scratch (no allocations allowed) ----------------
__device__ __align__(16) unsigned char g_xb[(size_t)NPTS * ROW_BYTES]; // 4 MB bf16
__device__ float g_sq[NPTS];
__device__ float g_part[NTRI];
__device__ int   g_is64;
__device__ unsigned int g_cnt;

#define CP16(d, s) \
    asm volatile("cp.async.cg.shared.global [%0], [%1], 16;" :: "r"(d), "l"(s) : "memory")
#define CPC()  asm volatile("cp.async.commit_group;" ::: "memory")
#define CPW1() asm volatile("cp.async.wait_group 1;" ::: "memory")
#define CPW0() asm volatile("cp.async.wait_group 0;" ::: "memory")

// ---------------------------------------------------------------------------
// Kernel 1: x -> bf16 (zero-padded), sq from the SAME bf16 values.
// Block 0 additionally: label-dtype detection + counter reset.
// ---------------------------------------------------------------------------
__global__ void prep_kernel(const float* __restrict__ x,
                            const int* __restrict__ lab32) {
    int row  = blockIdx.x * (TPB / 32) + (threadIdx.x >> 5);
    int lane = threadIdx.x & 31;
    int k0   = lane * 8;
    const float* xr = x + (size_t)row * D;
    float s = 0.f;
    uint32_t w[4];
#pragma unroll
    for (int p = 0; p < 4; p++) {
        int ka = k0 + 2 * p, kb = ka + 1;
        float f0 = (ka < D) ? xr[ka] : 0.f;
        float f1 = (kb < D) ? xr[kb] : 0.f;
        __nv_bfloat16 b0 = __float2bfloat16(f0);
        __nv_bfloat16 b1 = __float2bfloat16(f1);
        float g0 = __bfloat162float(b0), g1 = __bfloat162float(b1);
        s = fmaf(g0, g0, s);
        s = fmaf(g1, g1, s);
        w[p] = (uint32_t)__bfloat16_as_ushort(b0) |
               ((uint32_t)__bfloat16_as_ushort(b1) << 16);
    }
    *(uint4*)(g_xb + (size_t)row * ROW_BYTES + k0 * 2) = make_uint4(w[0], w[1], w[2], w[3]);
#pragma unroll
    for (int o = 16; o; o >>= 1) s += __shfl_xor_sync(0xffffffffu, s, o);
    if (lane == 0) g_sq[row] = s;

    if (blockIdx.x == 0) {  // label dtype detection + counter reset
        __shared__ int any;
        if (threadIdx.x == 0) { any = 0; g_cnt = 0; }
        __syncthreads();
        int a = 0;
        for (int i = 2 * threadIdx.x + 1; i < NPTS; i += 2 * TPB) a |= lab32[i];
        if (a) atomicOr(&any, 1);
        __syncthreads();
        if (threadIdx.x == 0) g_is64 = (any == 0) ? 1 : 0;
    }
}

// ---------------------------------------------------------------------------
// Chunk prefetch: 128B of K per row for A(128) + B(128) rows into stage buf.
// ---------------------------------------------------------------------------
__device__ __forceinline__ void prefetch(uint32_t dynA, int buf,
                                         const unsigned char* gA,
                                         const unsigned char* gB, int ch, int t) {
    uint32_t so = buf ? (uint32_t)STAGE : 0u;
#pragma unroll
    for (int p = 0; p < 8; p++) {
        int G = t + TPB * p;                 // 0..2047
        int isB  = (G >= 1024);
        int L    = isB ? (G - 1024) : G;
        int row  = L >> 3, g = L & 7;
        const unsigned char* gp = isB ? gB : gA;
        uint32_t soff = so + (isB ? (uint32_t)ACH : 0u) + row * SROW + g * 16;
        size_t   goff = (size_t)row * ROW_BYTES + (size_t)ch * 128 + (size_t)g * 16;
        CP16(dynA + soff, gp + goff);
    }
    CPC();
}

// ---------------------------------------------------------------------------
// Kernel 2: triangular grid of 128x128 Gram tiles, mma.sync bf16 m16n8k16.
// Chunked cp.async double buffer + explicit register double-buffering of
// ldmatrix fragments (R13 mainloop). Register-neutral lean epilogue.
// ---------------------------------------------------------------------------
__global__ void __launch_bounds__(TPB, 2)
pair_kernel(const int* __restrict__ lab32, float* __restrict__ out) {
    extern __shared__ __align__(128) unsigned char dyn[];
    __shared__ float sqA[TM], sqB[TM];
    __shared__ int   lA[TM], lB[TM];
    __shared__ float red[TPB / 32];
    __shared__ int    s_last;
    __shared__ double dred[TPB];

    const int t    = threadIdx.x;
    const int wid  = t >> 5;
    const int lane = t & 31;

    // linearized upper-triangle map: blockIdx.x -> (ti, tj), ti <= tj
    int bl = blockIdx.x, ti = 0;
    while (bl >= NT - ti) { bl -= NT - ti; ti++; }
    const int tj = ti + bl;

    const uint32_t dynA = (uint32_t)__cvta_generic_to_shared(dyn);
    const unsigned char* gA = g_xb + (size_t)(ti * TM) * ROW_BYTES;
    const unsigned char* gB = g_xb + (size_t)(tj * TM) * ROW_BYTES;

    prefetch(dynA, 0, gA, gB, 0, t);
    prefetch(dynA, 1, gA, gB, 1, t);

    {
        int is64 = g_is64;
        if (t < TM) {
            int g = ti * TM + t;
            sqA[t] = g_sq[g];
            lA[t]  = is64 ? lab32[2 * g] : lab32[g];
        } else {
            int u = t - TM, g = tj * TM + u;
            sqB[u] = g_sq[g];
            lB[u]  = is64 ? lab32[2 * g] : lab32[g];
        }
    }

    const int warp_m = wid >> 1;   // 0..3 -> 32 rows
    const int warp_n = wid & 1;    // 0..1 -> 64 cols

    // Padded-stride (conflict-free) immediate-offset ldmatrix bases.
    uint32_t abase[2];
#pragma unroll
    for (int f = 0; f < 2; f++)
        abase[f] = dynA + (warp_m * 32 + f * 16 + (lane & 15)) * SROW
                 + ((lane >> 4) << 4);
    uint32_t bbase[4];
#pragma unroll
    for (int h = 0; h < 4; h++)
        bbase[h] = dynA + ACH
                 + (warp_n * 64 + h * 16 + (lane & 7) + ((lane >> 4) << 3)) * SROW
                 + (((lane >> 3) & 1) << 4);

    float acc[2][8][4];
#pragma unroll
    for (int f = 0; f < 2; f++)
#pragma unroll
        for (int j = 0; j < 8; j++)
#pragma unroll
            for (int e = 0; e < 4; e++) acc[f][j][e] = 0.f;

    uint32_t aF[2][2][4];   // [kstep parity][f][frag]
    uint32_t bF[2][4];      // [stage parity][frag]

#define LDA_M(buf, kk)                                                            \
    { _Pragma("unroll")                                                           \
      for (int f = 0; f < 2; f++)                                                 \
          asm volatile("ldmatrix.sync.aligned.m8n8.x4.shared.b16 {%0,%1,%2,%3}, [%4];" \
              : "=r"(aF[buf][f][0]), "=r"(aF[buf][f][1]),                         \
                "=r"(aF[buf][f][2]), "=r"(aF[buf][f][3])                          \
              : "r"(abase[f] + bofs + (kk) * 32)); }

#define LDB_M(slot, kk, hh)                                                       \
    asm volatile("ldmatrix.sync.aligned.m8n8.x4.shared.b16 {%0,%1,%2,%3}, [%4];"  \
        : "=r"(bF[slot][0]), "=r"(bF[slot][1]), "=r"(bF[slot][2]), "=r"(bF[slot][3]) \
        : "r"(bbase[hh] + bofs + (kk) * 32))

#define MMA4_M(abuf, slot, hh)                                                    \
    { _Pragma("unroll")                                                           \
      for (int f = 0; f < 2; f++) {                                               \
          asm volatile(                                                           \
              "mma.sync.aligned.m16n8k16.row.col.f32.bf16.bf16.f32 "              \
              "{%0,%1,%2,%3}, {%4,%5,%6,%7}, {%8,%9}, {%0,%1,%2,%3};"             \
              : "+f"(acc[f][2 * (hh)][0]), "+f"(acc[f][2 * (hh)][1]),             \
                "+f"(acc[f][2 * (hh)][2]), "+f"(acc[f][2 * (hh)][3])              \
              : "r"(aF[abuf][f][0]), "r"(aF[abuf][f][1]),                         \
                "r"(aF[abuf][f][2]), "r"(aF[abuf][f][3]),                         \
                "r"(bF[slot][0]), "r"(bF[slot][1]));                              \
          asm volatile(                                                           \
              "mma.sync.aligned.m16n8k16.row.col.f32.bf16.bf16.f32 "              \
              "{%0,%1,%2,%3}, {%4,%5,%6,%7}, {%8,%9}, {%0,%1,%2,%3};"             \
              : "+f"(acc[f][2 * (hh) + 1][0]), "+f"(acc[f][2 * (hh) + 1][1]),     \
                "+f"(acc[f][2 * (hh) + 1][2]), "+f"(acc[f][2 * (hh) + 1][3])      \
              : "r"(aF[abuf][f][0]), "r"(aF[abuf][f][1]),                         \
                "r"(aF[abuf][f][2]), "r"(aF[abuf][f][3]),                         \
                "r"(bF[slot][2]), "r"(bF[slot][3]));                              \
      } }

// Pipelined chunk: NS ksteps = 4*NS h-stages; LDSM for s+1 precedes MMA for s.
#define CHUNK_M(NS)                                                               \
    do {                                                                          \
        LDA_M(0, 0);                                                              \
        LDB_M(0, 0, 0);                                                           \
        _Pragma("unroll")                                                         \
        for (int s = 0; s < 4 * (NS); s++) {                                      \
            int ks = s >> 2, h = s & 3;                                           \
            int sn = s + 1, kn = sn >> 2, hn = sn & 3;                            \
            if (sn < 4 * (NS)) {                                                  \
                if (hn == 0) LDA_M(kn & 1, kn);                                   \
                LDB_M(sn & 1, kn, hn);                                            \
            }                                                                     \
            MMA4_M(ks & 1, s & 1, h);                                             \
        }                                                                         \
    } while (0)

#pragma unroll
    for (int ch = 0; ch < 4; ch++) {
        if (ch < 3) CPW1(); else CPW0();
        __syncthreads();
        const uint32_t bofs = (ch & 1) ? (uint32_t)STAGE : 0u;
        if (ch < 3) CHUNK_M(4); else CHUNK_M(1);   // 13 k-steps total
        __syncthreads();
        if (ch < 2) prefetch(dynA, ch & 1, gA, gB, ch + 2, t);
    }
#undef CHUNK_M
#undef MMA4_M
#undef LDB_M
#undef LDA_M

    // ---- Epilogue: hoist only sA4/lA4 (reg-neutral); diag/off-diag split ----
    const int qrow = lane >> 2;
    const int qcol = (lane & 3) * 2;
    float sA4[4]; int lA4[4];
#pragma unroll
    for (int r = 0; r < 4; r++) {
        int m = warp_m * 32 + (r >> 1) * 16 + (r & 1) * 8 + qrow;
        sA4[r] = sqA[m];
        lA4[r] = lA[m];
    }
    float ps[4] = {0.f, 0.f, 0.f, 0.f};
    if (ti != tj) {  // 2016/2080 tiles: no predicate, no fmax, no index math
#pragma unroll
        for (int f = 0; f < 2; f++)
#pragma unroll
            for (int j = 0; j < 8; j++) {
                int n0 = warp_n * 64 + j * 8 + qcol;
#pragma unroll
                for (int e = 0; e < 4; e++) {
                    int r = f * 2 + (e >> 1);
                    int n = n0 + (e & 1);
                    float d2 = fmaf(-2.f, acc[f][j][e], sA4[r] + sqB[n]);
                    float dist;
                    asm("sqrt.approx.f32 %0, %1;" : "=f"(dist) : "f"(d2));
                    ps[e] += (lA4[r] == lB[n]) ? dist : -dist;
                }
            }
    } else {         // 64 diagonal tiles: strict upper predicate + clamp
#pragma unroll
        for (int f = 0; f < 2; f++)
#pragma unroll
            for (int j = 0; j < 8; j++) {
                int n0 = warp_n * 64 + j * 8 + qcol;
#pragma unroll
                for (int e = 0; e < 4; e++) {
                    int r = f * 2 + (e >> 1);
                    int n = n0 + (e & 1);
                    int m_loc = warp_m * 32 + (r >> 1) * 16 + (r & 1) * 8 + qrow;
                    float d2 = fmaxf(fmaf(-2.f, acc[f][j][e], sA4[r] + sqB[n]), 0.f);
                    float dist;
                    asm("sqrt.approx.f32 %0, %1;" : "=f"(dist) : "f"(d2));
                    float sgn = (lA4[r] == lB[n]) ? dist : -dist;
                    if (n > m_loc) ps[e] += sgn;
                }
            }
    }
    float lsum = (ps[0] + ps[1]) + (ps[2] + ps[3]);
#pragma unroll
    for (int o = 16; o; o >>= 1) lsum += __shfl_xor_sync(0xffffffffu, lsum, o);
    if (lane == 0) red[wid] = lsum;
    __syncthreads();
    if (t == 0) {
        float s = 0.f;
#pragma unroll
        for (int w = 0; w < TPB / 32; w++) s += red[w];
        g_part[blockIdx.x] = s;
    }

    // ---- last-CTA-done fused final reduction (deterministic order) ----
    __threadfence();
    if (t == 0) {
        unsigned old = atomicAdd(&g_cnt, 1u);
        s_last = (old == NTRI - 1) ? 1 : 0;
    }
    __syncthreads();
    if (s_last) {
        __threadfence();
        double a = 0.0;
        for (int i = t; i < NTRI; i += TPB) a += (double)g_part[i];
        dred[t] = a;
        __syncthreads();
        for (int o = TPB / 2; o; o >>= 1) {
            if (t < o) dred[t] += dred[t + o];
            __syncthreads();
        }
        if (t == 0) out[0] = (float)(2.0 * dred[0] / (double)NPTS);
    }
}

// ---------------------------------------------------------------------------
extern "C" void kernel_launch(void* const* d_in, const int* in_sizes, int n_in,
                              void* d_out, int out_size) {
    const float* x     = (const float*)d_in[0];
    const int*   lab32 = (const int*)d_in[1];
    float*       outp  = (float*)d_out;

    cudaFuncSetAttribute(pair_kernel, cudaFuncAttributeMaxDynamicSharedMemorySize,
                         SMEM_DYN);

    prep_kernel<<<NPTS / (TPB / 32), TPB>>>(x, lab32);
    pair_kernel<<<NTRI, TPB, SMEM_DYN>>>(lab32, outp);
}